// round 2
// baseline (speedup 1.0000x reference)
#include <cuda_runtime.h>
#include <math.h>

#define NN   40000
#define NE   640000
#define FIN  64
#define FOUT 128
#define NP   12
#define FTOT 768      /* FIN*NP */
#define GC   512      /* 4*FOUT */
#define BM   32       /* nodes per block in step kernel */

// ---------------- device scratch (static, no allocations) ----------------
__device__ float d_deg[NN];
__device__ float d_dinv[NN];
__device__ int   d_counts[NN];
__device__ int   d_cursor[NN];
__device__ int   d_offsets[NN + 1];
__device__ int   d_csr[NE];
__device__ float d_S[NP * NN * FIN];   // [t][n][k]
__device__ float d_H[NN * FOUT];
__device__ float d_C[NN * FOUT];
__device__ float d_W1[FIN * GC];       // folded W_x @ W_h_top
__device__ float d_W2[FOUT * GC];      // W_h_bottom
__device__ float d_bias[GC];
__device__ float d_probs[NP];

struct GateW {
    const float* wx[4];
    const float* bx[4];
    const float* wh[4];
    const float* bh[4];
    const float* att;
};

// ---------------- packed f32x2 helpers (FFMA2) ----------------
__device__ __forceinline__ unsigned long long pk2(float x) {
    unsigned long long r;
    asm("mov.b64 %0, {%1, %1};" : "=l"(r) : "f"(x));
    return r;
}
__device__ __forceinline__ unsigned long long f2fma(unsigned long long a,
                                                    unsigned long long b,
                                                    unsigned long long c) {
    unsigned long long d;
    asm("fma.rn.f32x2 %0, %1, %2, %3;" : "=l"(d) : "l"(a), "l"(b), "l"(c));
    return d;
}
__device__ __forceinline__ float2 up2(unsigned long long v) {
    float2 r;
    asm("mov.b64 {%0, %1}, %2;" : "=f"(r.x), "=f"(r.y) : "l"(v));
    return r;
}

// ---------------- kernels ----------------
__global__ void zero_kernel() {
    int i = blockIdx.x * blockDim.x + threadIdx.x;
    int stride = gridDim.x * blockDim.x;
    for (int idx = i; idx < NN * FOUT; idx += stride) { d_H[idx] = 0.f; d_C[idx] = 0.f; }
    for (int idx = i; idx < NN; idx += stride) { d_deg[idx] = 0.f; d_counts[idx] = 0; d_cursor[idx] = 0; }
}

__global__ void deg_kernel(const int* __restrict__ ei, const float* __restrict__ ew) {
    int i = blockIdx.x * blockDim.x + threadIdx.x;
    int stride = gridDim.x * blockDim.x;
    for (int e = i; e < NE; e += stride) {
        int c = ei[NE + e];
        atomicAdd(&d_deg[c], ew[e]);
        atomicAdd(&d_counts[c], 1);
    }
}

// dinv + exclusive scan of counts, single block, shuffle-based (few barriers)
__global__ __launch_bounds__(1024) void scan_kernel() {
    int tid = threadIdx.x;
    // dinv (deg from edges; +1 is the self-loop weight, always > 0)
    for (int n = tid; n < NN; n += 1024)
        d_dinv[n] = rsqrtf(d_deg[n] + 1.0f);

    const int CH = 40;                 // 1024*40 = 40960 >= NN
    int base = tid * CH;
    int sum = 0;
#pragma unroll 4
    for (int i = 0; i < CH; i++) {
        int idx = base + i;
        if (idx < NN) sum += d_counts[idx];
    }
    // block exclusive scan of per-thread sums
    int lane = tid & 31, wid = tid >> 5;
    int v = sum;
#pragma unroll
    for (int o = 1; o < 32; o <<= 1) {
        int t = __shfl_up_sync(0xffffffffu, v, o);
        if (lane >= o) v += t;
    }
    __shared__ int wsum[32];
    if (lane == 31) wsum[wid] = v;
    __syncthreads();
    if (wid == 0) {
        int w = wsum[lane];
#pragma unroll
        for (int o = 1; o < 32; o <<= 1) {
            int t = __shfl_up_sync(0xffffffffu, w, o);
            if (lane >= o) w += t;
        }
        wsum[lane] = w;
    }
    __syncthreads();
    int excl = v - sum + (wid ? wsum[wid - 1] : 0);
    int run = excl;
#pragma unroll 4
    for (int i = 0; i < CH; i++) {
        int idx = base + i;
        if (idx < NN) { d_offsets[idx] = run; run += d_counts[idx]; }
    }
    if (tid == 1023) d_offsets[NN] = run;
}

__global__ void fill_kernel(const int* __restrict__ ei) {
    int i = blockIdx.x * blockDim.x + threadIdx.x;
    int stride = gridDim.x * blockDim.x;
    for (int e = i; e < NE; e += stride) {
        int c = ei[NE + e];
        int p = atomicAdd(&d_cursor[c], 1);
        d_csr[d_offsets[c] + p] = e;
    }
}

// merged prep: blocks [0,64) -> W1 rows, [64,192) -> W2 rows, 192 -> bias+probs
__global__ __launch_bounds__(512) void prep_kernel(GateW gw) {
    int b = blockIdx.x;
    int c = threadIdx.x;          // 0..511
    int g = c >> 7, j = c & 127;
    if (b < 64) {
        int k = b;
        const float* wx = gw.wx[g];
        const float* wh = gw.wh[g];
        float acc = 0.f;
#pragma unroll 8
        for (int m = 0; m < FOUT; m++)
            acc += wx[k * FOUT + m] * wh[m * FOUT + j];
        d_W1[k * GC + c] = acc;
    } else if (b < 192) {
        int k = b - 64;
        d_W2[k * GC + c] = gw.wh[g][(FOUT + k) * FOUT + j];
    } else {
        float acc = gw.bh[g][j];
        for (int m = 0; m < FOUT; m++)
            acc += gw.bx[g][m] * gw.wh[g][m * FOUT + j];
        d_bias[c] = acc;
        if (c == 0) {
            float a[NP], mx = -1e30f, s = 0.f;
            for (int t = 0; t < NP; t++) { a[t] = gw.att[t]; mx = fmaxf(mx, a[t]); }
            for (int t = 0; t < NP; t++) { a[t] = expf(a[t] - mx); s += a[t]; }
            for (int t = 0; t < NP; t++) d_probs[t] = a[t] / s;
        }
    }
}

// Gather-SpMM: S[t][n][fin], one block per node.
__global__ __launch_bounds__(768) void spmm_kernel(const float* __restrict__ X,
                                                   const int* __restrict__ ei,
                                                   const float* __restrict__ ew) {
    __shared__ int   srow[64];
    __shared__ float snrm[64];
    __shared__ float sval[FTOT];
    int n = blockIdx.x;
    int tid = threadIdx.x;
    float dn = d_dinv[n];
    float acc = dn * dn * X[n * FTOT + tid];   // self loop, weight 1
    int beg = d_offsets[n], end = d_offsets[n + 1];
    for (int eb = beg; eb < end; eb += 64) {
        int cnt = min(64, end - eb);
        if (tid < cnt) {
            int e = d_csr[eb + tid];
            int r = ei[e];
            srow[tid] = r;
            snrm[tid] = d_dinv[r] * ew[e] * dn;
        }
        __syncthreads();
#pragma unroll 4
        for (int i = 0; i < cnt; i++)
            acc += snrm[i] * X[srow[i] * FTOT + tid];
        __syncthreads();
    }
    sval[tid] = acc;
    __syncthreads();
    int t = tid >> 6, f = tid & 63;
    d_S[t * (NN * FIN) + n * FIN + f] = sval[f * NP + t];
}

// Fused per-period step: Z = [S_t | H] @ [W1; W2] + bias, then LSTM elementwise.
// Block: 32 nodes x 512 gate cols, 256 threads, each thread 8 nodes x 8 cols.
__global__ __launch_bounds__(256, 2) void step_kernel(int t, float* __restrict__ Hacc) {
    __shared__ __align__(16) float As[16][36];      // [kk][node], padded stride 36
    __shared__ __align__(16) float Bs[16 * GC];     // 32KB, reused as Z staging
    int tid = threadIdx.x;
    int tx = tid & 63;       // col group: cols tx*8 .. tx*8+7
    int r  = tid >> 6;       // node group: nodes r*8 .. r*8+7
    int node0 = blockIdx.x * BM;

    unsigned long long acc[8][4];
#pragma unroll
    for (int i = 0; i < 8; i++)
#pragma unroll
        for (int j = 0; j < 4; j++) acc[i][j] = 0ull;

    const float* Sbase = d_S + t * (NN * FIN) + node0 * FIN;
    const float* Hbase = d_H + node0 * FOUT;

    for (int kt = 0; kt < 12; kt++) {
        int k0 = kt * 16;
        // A tile: 32 nodes x 16 k, 512 values, 256 threads -> 2 each (coalesced 16-float runs)
#pragma unroll
        for (int v = tid; v < BM * 16; v += 256) {
            int nd = v >> 4, kk = v & 15;
            float val = (k0 < FIN) ? Sbase[nd * FIN + k0 + kk]
                                   : Hbase[nd * FOUT + (k0 - FIN) + kk];
            As[kk][nd] = val;
        }
        // B tile: 16x512 contiguous floats = 32KB
        {
            const float4* Bsrc = (const float4*)((k0 < FIN) ? (d_W1 + k0 * GC)
                                                            : (d_W2 + (k0 - FIN) * GC));
            float4* Bdst = (float4*)Bs;
#pragma unroll
            for (int i = 0; i < 8; i++) Bdst[i * 256 + tid] = Bsrc[i * 256 + tid];
        }
        __syncthreads();

#pragma unroll
        for (int kk = 0; kk < 16; kk++) {
            float4 a0 = *(const float4*)&As[kk][r * 8];
            float4 a1 = *(const float4*)&As[kk][r * 8 + 4];
            ulonglong2 b01 = *(const ulonglong2*)&Bs[kk * GC + tx * 8];
            ulonglong2 b23 = *(const ulonglong2*)&Bs[kk * GC + tx * 8 + 4];
            unsigned long long bb[4] = {b01.x, b01.y, b23.x, b23.y};
            float af[8] = {a0.x, a0.y, a0.z, a0.w, a1.x, a1.y, a1.z, a1.w};
#pragma unroll
            for (int i = 0; i < 8; i++) {
                unsigned long long aa = pk2(af[i]);
#pragma unroll
                for (int j = 0; j < 4; j++)
                    acc[i][j] = f2fma(aa, bb[j], acc[i][j]);
            }
        }
        __syncthreads();
    }

    float4 bias0 = *(const float4*)&d_bias[tx * 8];
    float4 bias1 = *(const float4*)&d_bias[tx * 8 + 4];
    float p = d_probs[t];

    // Epilogue in 2 halves of 16 nodes (Z staging reuses Bs = 32KB)
#pragma unroll
    for (int h = 0; h < 2; h++) {
        if ((r >> 1) == h) {
            int ndl0 = (r & 1) * 8;   // local node base within half
#pragma unroll
            for (int i = 0; i < 8; i++) {
                float2 z0 = up2(acc[i][0]), z1 = up2(acc[i][1]);
                float2 z2 = up2(acc[i][2]), z3 = up2(acc[i][3]);
                float4 w0 = make_float4(z0.x + bias0.x, z0.y + bias0.y,
                                        z1.x + bias0.z, z1.y + bias0.w);
                float4 w1 = make_float4(z2.x + bias1.x, z2.y + bias1.y,
                                        z3.x + bias1.z, z3.y + bias1.w);
                float4* zp = (float4*)&Bs[(ndl0 + i) * GC + tx * 8];
                zp[0] = w0; zp[1] = w1;
            }
        }
        __syncthreads();
#pragma unroll
        for (int rr = 0; rr < 8; rr++) {
            int it = rr * 256 + tid;       // 0..2047
            int ndl = it >> 7;             // local node in half
            int j   = it & 127;            // feature
            float zi = Bs[ndl * GC + j];
            float zf = Bs[ndl * GC + 128 + j];
            float zc = Bs[ndl * GC + 256 + j];
            float zo = Bs[ndl * GC + 384 + j];
            int gidx = (node0 + h * 16 + ndl) * FOUT + j;
            float I  = 1.f / (1.f + __expf(-zi));
            float F  = 1.f / (1.f + __expf(-zf));
            float Ct = tanhf(zc);
            float O  = 1.f / (1.f + __expf(-zo));
            float cn = F * d_C[gidx] + I * Ct;
            float hh = O * tanhf(cn);
            d_C[gidx] = cn;
            d_H[gidx] = hh;
            if (t == 0) Hacc[gidx] = p * hh;
            else        Hacc[gidx] += p * hh;
        }
        __syncthreads();
    }
}

// ---------------- launch ----------------
extern "C" void kernel_launch(void* const* d_in, const int* in_sizes, int n_in,
                              void* d_out, int out_size) {
    const float* X   = (const float*)d_in[0];
    const int*   ei  = (const int*)d_in[1];
    const float* ew  = (const float*)d_in[2];
    const float* att = (const float*)d_in[3];
    GateW gw;
    for (int g = 0; g < 4; g++) {
        gw.wx[g] = (const float*)d_in[4 + 4 * g];
        gw.bx[g] = (const float*)d_in[5 + 4 * g];
        gw.wh[g] = (const float*)d_in[6 + 4 * g];
        gw.bh[g] = (const float*)d_in[7 + 4 * g];
    }
    gw.att = att;
    float* out = (float*)d_out;

    zero_kernel<<<512, 256>>>();
    deg_kernel<<<640, 256>>>(ei, ew);
    scan_kernel<<<1, 1024>>>();
    fill_kernel<<<640, 256>>>(ei);
    prep_kernel<<<193, 512>>>(gw);
    spmm_kernel<<<NN, 768>>>(X, ei, ew);
    for (int t = 0; t < NP; t++)
        step_kernel<<<NN / BM, 256>>>(t, out);
}

// round 6
// speedup vs baseline: 1.3025x; 1.3025x over previous
#include <cuda_runtime.h>
#include <cuda_bf16.h>
#include <math.h>
#include <stdint.h>

#define NN   40000
#define NE   640000
#define FIN  64
#define FOUT 128
#define NP   12
#define FTOT 768
#define GC   512      /* 4*FOUT */
#define KTOT 192      /* FIN + FOUT */
#define HBUF (NN * FOUT)

// ---------------- device scratch ----------------
__device__ float d_deg[NN];
__device__ float d_dinv[NN];
__device__ int   d_counts[NN];
__device__ int   d_cursor[NN];
__device__ int   d_offsets[NN + 1];
__device__ int   d_csr[NE];
__device__ __nv_bfloat16 d_Sh[(size_t)NP * NN * FIN];
__device__ __nv_bfloat16 d_Sl[(size_t)NP * NN * FIN];
__device__ __nv_bfloat16 d_Hh[2 * HBUF];     // ping-pong: parity t&1 read, (t+1)&1 write
__device__ __nv_bfloat16 d_Hl[2 * HBUF];
__device__ float d_C[NN * FOUT];
__device__ float d_W1[FIN * GC];
__device__ float d_W2[FOUT * GC];
__device__ __nv_bfloat16 d_Wth[GC * KTOT];   // permuted-transposed [c'][k], hi
__device__ __nv_bfloat16 d_Wtl[GC * KTOT];   // permuted-transposed [c'][k], lo
__device__ float d_biasP[GC];                 // permuted bias
__device__ float d_probs[NP];

struct GateW {
    const float* wx[4];
    const float* bx[4];
    const float* wh[4];
    const float* bh[4];
    const float* att;
};

// ---------------- PTX helpers (baseline ISA only) ----------------
__device__ __forceinline__ uint32_t smem_u32(const void* p) {
    uint32_t a;
    asm("{ .reg .u64 t; cvta.to.shared.u64 t, %1; cvt.u32.u64 %0, t; }" : "=r"(a) : "l"(p));
    return a;
}
__device__ __forceinline__ void cp16(uint32_t dst, const void* src) {
    asm volatile("cp.async.cg.shared.global [%0], [%1], 16;" :: "r"(dst), "l"(src));
}
#define CP_COMMIT() asm volatile("cp.async.commit_group;" ::: "memory")
#define CP_WAIT(n)  asm volatile("cp.async.wait_group %0;" :: "n"(n) : "memory")

__device__ __forceinline__ void ldsm4(uint32_t a, uint32_t& r0, uint32_t& r1,
                                      uint32_t& r2, uint32_t& r3) {
    asm volatile("ldmatrix.sync.aligned.m8n8.x4.shared.b16 {%0,%1,%2,%3}, [%4];"
        : "=r"(r0), "=r"(r1), "=r"(r2), "=r"(r3) : "r"(a));
}
__device__ __forceinline__ void mma16816(float* d, const uint32_t* a, const uint32_t* b) {
    asm volatile("mma.sync.aligned.m16n8k16.row.col.f32.bf16.bf16.f32 "
        "{%0,%1,%2,%3}, {%4,%5,%6,%7}, {%8,%9}, {%0,%1,%2,%3};"
        : "+f"(d[0]), "+f"(d[1]), "+f"(d[2]), "+f"(d[3])
        : "r"(a[0]), "r"(a[1]), "r"(a[2]), "r"(a[3]), "r"(b[0]), "r"(b[1]));
}

// ---------------- small kernels ----------------
__global__ void zero_kernel() {
    int i = blockIdx.x * blockDim.x + threadIdx.x;
    int stride = gridDim.x * blockDim.x;
    for (int idx = i; idx < NN * FOUT; idx += stride) d_C[idx] = 0.f;
    for (int idx = i; idx < 2 * HBUF; idx += stride) {
        d_Hh[idx] = __nv_bfloat16(0.f);
        d_Hl[idx] = __nv_bfloat16(0.f);
    }
    for (int idx = i; idx < NN; idx += stride) { d_deg[idx] = 0.f; d_counts[idx] = 0; d_cursor[idx] = 0; }
}

__global__ void deg_kernel(const int* __restrict__ ei, const float* __restrict__ ew) {
    int i = blockIdx.x * blockDim.x + threadIdx.x;
    int stride = gridDim.x * blockDim.x;
    for (int e = i; e < NE; e += stride) {
        int c = ei[NE + e];
        atomicAdd(&d_deg[c], ew[e]);
        atomicAdd(&d_counts[c], 1);
    }
}

__global__ __launch_bounds__(1024) void scan_kernel() {
    int tid = threadIdx.x;
    for (int n = tid; n < NN; n += 1024)
        d_dinv[n] = rsqrtf(d_deg[n] + 1.0f);
    const int CH = 40;
    int base = tid * CH;
    int sum = 0;
#pragma unroll 4
    for (int i = 0; i < CH; i++) { int idx = base + i; if (idx < NN) sum += d_counts[idx]; }
    int lane = tid & 31, wid = tid >> 5;
    int v = sum;
#pragma unroll
    for (int o = 1; o < 32; o <<= 1) { int t = __shfl_up_sync(0xffffffffu, v, o); if (lane >= o) v += t; }
    __shared__ int wsum[32];
    if (lane == 31) wsum[wid] = v;
    __syncthreads();
    if (wid == 0) {
        int w = wsum[lane];
#pragma unroll
        for (int o = 1; o < 32; o <<= 1) { int t = __shfl_up_sync(0xffffffffu, w, o); if (lane >= o) w += t; }
        wsum[lane] = w;
    }
    __syncthreads();
    int excl = v - sum + (wid ? wsum[wid - 1] : 0);
    int run = excl;
#pragma unroll 4
    for (int i = 0; i < CH; i++) {
        int idx = base + i;
        if (idx < NN) { d_offsets[idx] = run; run += d_counts[idx]; }
    }
    if (tid == 1023) d_offsets[NN] = run;
}

__global__ void fill_kernel(const int* __restrict__ ei) {
    int i = blockIdx.x * blockDim.x + threadIdx.x;
    int stride = gridDim.x * blockDim.x;
    for (int e = i; e < NE; e += stride) {
        int c = ei[NE + e];
        int p = atomicAdd(&d_cursor[c], 1);
        d_csr[d_offsets[c] + p] = e;
    }
}

__global__ __launch_bounds__(512) void prep_kernel(GateW gw) {
    int b = blockIdx.x;
    int c = threadIdx.x;
    int g = c >> 7, j = c & 127;
    if (b < 64) {
        int k = b;
        const float* wx = gw.wx[g];
        const float* wh = gw.wh[g];
        float acc = 0.f;
#pragma unroll 8
        for (int m = 0; m < FOUT; m++) acc += wx[k * FOUT + m] * wh[m * FOUT + j];
        d_W1[k * GC + c] = acc;
    } else if (b < 192) {
        int k = b - 64;
        d_W2[k * GC + c] = gw.wh[g][(FOUT + k) * FOUT + j];
    } else {
        float acc = gw.bh[g][j];
        for (int m = 0; m < FOUT; m++) acc += gw.bx[g][m] * gw.wh[g][m * FOUT + j];
        int cg = j >> 5, jj = j & 31;
        d_biasP[cg * 128 + g * 32 + jj] = acc;
        if (c == 0) {
            float a[NP], mx = -1e30f, s = 0.f;
            for (int t = 0; t < NP; t++) { a[t] = gw.att[t]; mx = fmaxf(mx, a[t]); }
            for (int t = 0; t < NP; t++) { a[t] = expf(a[t] - mx); s += a[t]; }
            for (int t = 0; t < NP; t++) d_probs[t] = a[t] / s;
        }
    }
}

// transpose + permute + bf16 hi/lo split of [W1;W2] -> Wt[c'][k]
__global__ __launch_bounds__(192) void wsplit_kernel() {
    int c = blockIdx.x;      // original col 0..511
    int k = threadIdx.x;     // 0..191
    float w = (k < FIN) ? d_W1[k * GC + c] : d_W2[(k - FIN) * GC + c];
    __nv_bfloat16 hi = __float2bfloat16(w);
    float lo = w - __bfloat162float(hi);
    int gate = c >> 7, j = c & 127;
    int cg = j >> 5, jj = j & 31;
    int cp = cg * 128 + gate * 32 + jj;
    d_Wth[cp * KTOT + k] = hi;
    d_Wtl[cp * KTOT + k] = __float2bfloat16(lo);
}

__global__ __launch_bounds__(768) void spmm_kernel(const float* __restrict__ X,
                                                   const int* __restrict__ ei,
                                                   const float* __restrict__ ew) {
    __shared__ int   srow[64];
    __shared__ float snrm[64];
    __shared__ float sval[FTOT];
    int n = blockIdx.x;
    int tid = threadIdx.x;
    float dn = d_dinv[n];
    float acc = dn * dn * X[n * FTOT + tid];
    int beg = d_offsets[n], end = d_offsets[n + 1];
    for (int eb = beg; eb < end; eb += 64) {
        int cnt = min(64, end - eb);
        if (tid < cnt) {
            int e = d_csr[eb + tid];
            int r = ei[e];
            srow[tid] = r;
            snrm[tid] = d_dinv[r] * ew[e] * dn;
        }
        __syncthreads();
#pragma unroll 4
        for (int i = 0; i < cnt; i++)
            acc += snrm[i] * X[srow[i] * FTOT + tid];
        __syncthreads();
    }
    sval[tid] = acc;
    __syncthreads();
    int t = tid >> 6, f = tid & 63;
    float val = sval[f * NP + t];
    __nv_bfloat16 hi = __float2bfloat16(val);
    size_t o = (size_t)t * NN * FIN + (size_t)n * FIN + f;
    d_Sh[o] = hi;
    d_Sl[o] = __float2bfloat16(val - __bfloat162float(hi));
}

// ---------------- HMMA step kernel ----------------
// Grid: (313 node-groups, 4 col-groups). CTA: 128 nodes x 128 permuted cols.
// 8 warps, warp tile 32x64. K=192 in 12 chunks of 16, cp.async double-buffered.
// H is ping-pong buffered across steps: read parity t&1, write parity (t+1)&1
// (eliminates the same-launch reader/writer race across col-group CTAs).
#define BUFSZ   24576
#define ASTRIDE 48
#define ZPAD    132
#define SMEM_TOT (2 * BUFSZ + 128 * ZPAD * 4)

__device__ __forceinline__ void load_chunk(uint32_t sb, int buf, int c, int t,
                                           int node0, int g, int tid) {
    uint32_t ab = sb + buf * BUFSZ;
    const __nv_bfloat16* Hh = d_Hh + (size_t)(t & 1) * HBUF;
    const __nv_bfloat16* Hl = d_Hl + (size_t)(t & 1) * HBUF;
#pragma unroll
    for (int i = 0; i < 2; i++) {
        int op = tid + 256 * i;          // 0..511
        int row = op >> 2;
        int s = (op >> 1) & 1;
        int half = op & 1;
        int node = min(node0 + row, NN - 1);
        const __nv_bfloat16* src;
        if (c < 4) src = (s ? d_Sl : d_Sh) + (size_t)t * NN * FIN + (size_t)node * FIN + c * 16 + half * 8;
        else       src = (s ? Hl : Hh) + (size_t)node * FOUT + (c - 4) * 16 + half * 8;
        cp16(ab + s * 6144 + row * ASTRIDE + half * 16, src);
    }
#pragma unroll
    for (int i = 0; i < 2; i++) {
        int op = tid + 256 * i;
        int row = op >> 2;
        int s = (op >> 1) & 1;
        int half = op & 1;
        const __nv_bfloat16* src = (s ? d_Wtl : d_Wth) + (size_t)(g * 128 + row) * KTOT + c * 16 + half * 8;
        cp16(ab + 12288 + s * 6144 + row * ASTRIDE + half * 16, src);
    }
}

__global__ __launch_bounds__(256) void step_gemm_kernel(int t, float* __restrict__ Hacc) {
    extern __shared__ char smem[];
    uint32_t sb = smem_u32(smem);
    int tid = threadIdx.x;
    int lane = tid & 31, wid = tid >> 5;
    int node0 = blockIdx.x * 128;
    int g = blockIdx.y;

    int wr = wid >> 1, wc = wid & 1;
    int m0 = wr * 32, n0 = wc * 64;

    float acc[2][8][4];
#pragma unroll
    for (int mt = 0; mt < 2; mt++)
#pragma unroll
        for (int nt = 0; nt < 8; nt++)
#pragma unroll
            for (int u = 0; u < 4; u++) acc[mt][nt][u] = 0.f;

    int arow = (lane & 7) + ((lane >> 3) & 1) * 8;
    int akh  = lane >> 4;
    int brow = (lane & 7) + (lane >> 4) * 8;
    int bkh  = (lane >> 3) & 1;

    load_chunk(sb, 0, 0, t, node0, g, tid);
    CP_COMMIT();

    for (int c = 0; c < 12; c++) {
        if (c < 11) {
            load_chunk(sb, (c + 1) & 1, c + 1, t, node0, g, tid);
            CP_COMMIT();
            CP_WAIT(1);
        } else {
            CP_WAIT(0);
        }
        __syncthreads();

        uint32_t ab = sb + (c & 1) * BUFSZ;
        uint32_t bb = ab + 12288;

        uint32_t af[2][2][4];
#pragma unroll
        for (int s = 0; s < 2; s++)
#pragma unroll
            for (int mt = 0; mt < 2; mt++)
                ldsm4(ab + s * 6144 + (m0 + mt * 16 + arow) * ASTRIDE + akh * 16,
                      af[s][mt][0], af[s][mt][1], af[s][mt][2], af[s][mt][3]);

        uint32_t bfr[2][8][2];
#pragma unroll
        for (int s = 0; s < 2; s++)
#pragma unroll
            for (int u = 0; u < 4; u++) {
                uint32_t r0, r1, r2, r3;
                ldsm4(bb + s * 6144 + (n0 + u * 16 + brow) * ASTRIDE + bkh * 16, r0, r1, r2, r3);
                bfr[s][2 * u][0] = r0; bfr[s][2 * u][1] = r1;
                bfr[s][2 * u + 1][0] = r2; bfr[s][2 * u + 1][1] = r3;
            }

        // 3 terms: (Ah,Bh), (Ah,Bl), (Al,Bh)
#pragma unroll
        for (int term = 0; term < 3; term++) {
            int sa = (term == 2) ? 1 : 0;
            int sbt = (term == 1) ? 1 : 0;
#pragma unroll
            for (int mt = 0; mt < 2; mt++)
#pragma unroll
                for (int nt = 0; nt < 8; nt++)
                    mma16816(acc[mt][nt], af[sa][mt], bfr[sbt][nt]);
        }
        __syncthreads();
    }

    // ---- stage Z to SMEM ----
    float* Zs = (float*)(smem + 2 * BUFSZ);
    int zr = lane >> 2, zc = (lane & 3) * 2;
#pragma unroll
    for (int mt = 0; mt < 2; mt++)
#pragma unroll
        for (int nt = 0; nt < 8; nt++) {
            int r0 = m0 + mt * 16 + zr, c0 = n0 + nt * 8 + zc;
            Zs[r0 * ZPAD + c0]     = acc[mt][nt][0];
            Zs[r0 * ZPAD + c0 + 1] = acc[mt][nt][1];
            Zs[(r0 + 8) * ZPAD + c0]     = acc[mt][nt][2];
            Zs[(r0 + 8) * ZPAD + c0 + 1] = acc[mt][nt][3];
        }
    __syncthreads();

    // ---- fused LSTM epilogue ----
    __nv_bfloat16* Hh_n = d_Hh + (size_t)((t + 1) & 1) * HBUF;
    __nv_bfloat16* Hl_n = d_Hl + (size_t)((t + 1) & 1) * HBUF;
    int jj = tid & 31;
    float bI = d_biasP[g * 128 + jj];
    float bF = d_biasP[g * 128 + 32 + jj];
    float bCt = d_biasP[g * 128 + 64 + jj];
    float bO = d_biasP[g * 128 + 96 + jj];
    float p = d_probs[t];

#pragma unroll
    for (int r = 0; r < 16; r++) {
        int m = (tid >> 5) + 8 * r;
        int node = node0 + m;
        if (node < NN) {
            float zi = Zs[m * ZPAD + jj] + bI;
            float zf = Zs[m * ZPAD + 32 + jj] + bF;
            float zc = Zs[m * ZPAD + 64 + jj] + bCt;
            float zo = Zs[m * ZPAD + 96 + jj] + bO;
            float I  = 1.f / (1.f + __expf(-zi));
            float F  = 1.f / (1.f + __expf(-zf));
            float Ct = 1.f - 2.f / (__expf(2.f * zc) + 1.f);
            float O  = 1.f / (1.f + __expf(-zo));
            int gidx = node * FOUT + g * 32 + jj;
            float cn = F * d_C[gidx] + I * Ct;
            float hh = O * (1.f - 2.f / (__expf(2.f * cn) + 1.f));
            d_C[gidx] = cn;
            __nv_bfloat16 hi = __float2bfloat16(hh);
            Hh_n[gidx] = hi;
            Hl_n[gidx] = __float2bfloat16(hh - __bfloat162float(hi));
            if (t == 0) Hacc[gidx] = p * hh;
            else        Hacc[gidx] += p * hh;
        }
    }
}

// ---------------- launch ----------------
extern "C" void kernel_launch(void* const* d_in, const int* in_sizes, int n_in,
                              void* d_out, int out_size) {
    const float* X   = (const float*)d_in[0];
    const int*   ei  = (const int*)d_in[1];
    const float* ew  = (const float*)d_in[2];
    const float* att = (const float*)d_in[3];
    GateW gw;
    for (int g = 0; g < 4; g++) {
        gw.wx[g] = (const float*)d_in[4 + 4 * g];
        gw.bx[g] = (const float*)d_in[5 + 4 * g];
        gw.wh[g] = (const float*)d_in[6 + 4 * g];
        gw.bh[g] = (const float*)d_in[7 + 4 * g];
    }
    gw.att = att;
    float* out = (float*)d_out;

    cudaFuncSetAttribute(step_gemm_kernel, cudaFuncAttributeMaxDynamicSharedMemorySize, SMEM_TOT);

    zero_kernel<<<512, 256>>>();
    deg_kernel<<<640, 256>>>(ei, ew);
    scan_kernel<<<1, 1024>>>();
    fill_kernel<<<640, 256>>>(ei);
    prep_kernel<<<193, 512>>>(gw);
    wsplit_kernel<<<GC, KTOT>>>();
    spmm_kernel<<<NN, 768>>>(X, ei, ew);
    dim3 grid((NN + 127) / 128, 4);
    for (int t = 0; t < NP; t++)
        step_gemm_kernel<<<grid, 256, SMEM_TOT>>>(t, out);
}

// round 7
// speedup vs baseline: 1.4976x; 1.1498x over previous
#include <cuda_runtime.h>
#include <math.h>
#include <stdint.h>

#define NN   40000
#define NE   640000
#define FIN  64
#define FOUT 128
#define NP   12
#define FTOT 768
#define GC   512      /* 4*FOUT */
#define KTOT 192
#define BN   64       /* nodes per step CTA */

// ---------------- device scratch ----------------
__device__ float d_deg[NN];
__device__ float d_dinv[NN];
__device__ int   d_counts[NN];
__device__ int   d_cursor[NN];
__device__ int   d_offsets[NN + 1];
__device__ int   d_csr[NE];
__device__ float d_S[(size_t)NP * NN * FIN];   // [t][n][k] fp32
__device__ float d_H[NN * FOUT];
__device__ float d_C[NN * FOUT];
__device__ float d_W1[FIN * GC];               // folded W_x @ W_h_top
__device__ float d_W2[FOUT * GC];              // W_h_bottom
__device__ float d_bias[GC];
__device__ float d_probs[NP];

struct GateW {
    const float* wx[4];
    const float* bx[4];
    const float* wh[4];
    const float* bh[4];
    const float* att;
};

// ---------------- packed f32x2 helpers ----------------
__device__ __forceinline__ unsigned long long pk2(float x) {
    unsigned long long r;
    asm("mov.b64 %0, {%1, %1};" : "=l"(r) : "f"(x));
    return r;
}
__device__ __forceinline__ unsigned long long pack2(float lo, float hi) {
    unsigned long long r;
    asm("mov.b64 %0, {%1, %2};" : "=l"(r) : "f"(lo), "f"(hi));
    return r;
}
__device__ __forceinline__ unsigned long long f2fma(unsigned long long a,
                                                    unsigned long long b,
                                                    unsigned long long c) {
    unsigned long long d;
    asm("fma.rn.f32x2 %0, %1, %2, %3;" : "=l"(d) : "l"(a), "l"(b), "l"(c));
    return d;
}
__device__ __forceinline__ float2 up2(unsigned long long v) {
    float2 r;
    asm("mov.b64 {%0, %1}, %2;" : "=f"(r.x), "=f"(r.y) : "l"(v));
    return r;
}

// ---------------- async copy helpers ----------------
__device__ __forceinline__ uint32_t smem_u32(const void* p) {
    uint32_t a;
    asm("{ .reg .u64 t; cvta.to.shared.u64 t, %1; cvt.u32.u64 %0, t; }" : "=r"(a) : "l"(p));
    return a;
}
__device__ __forceinline__ void cp16(uint32_t dst, const void* src) {
    asm volatile("cp.async.cg.shared.global [%0], [%1], 16;" :: "r"(dst), "l"(src));
}
#define CP_COMMIT() asm volatile("cp.async.commit_group;" ::: "memory")
#define CP_WAIT(n)  asm volatile("cp.async.wait_group %0;" :: "n"(n) : "memory")

// ---------------- small kernels ----------------
__global__ void zero_kernel() {
    int i = blockIdx.x * blockDim.x + threadIdx.x;
    int stride = gridDim.x * blockDim.x;
    for (int idx = i; idx < NN * FOUT; idx += stride) { d_H[idx] = 0.f; d_C[idx] = 0.f; }
    for (int idx = i; idx < NN; idx += stride) { d_deg[idx] = 0.f; d_counts[idx] = 0; d_cursor[idx] = 0; }
}

__global__ void deg_kernel(const int* __restrict__ ei, const float* __restrict__ ew) {
    int i = blockIdx.x * blockDim.x + threadIdx.x;
    int stride = gridDim.x * blockDim.x;
    for (int e = i; e < NE; e += stride) {
        int c = ei[NE + e];
        atomicAdd(&d_deg[c], ew[e]);
        atomicAdd(&d_counts[c], 1);
    }
}

__global__ __launch_bounds__(1024) void scan_kernel() {
    int tid = threadIdx.x;
    for (int n = tid; n < NN; n += 1024)
        d_dinv[n] = rsqrtf(d_deg[n] + 1.0f);
    const int CH = 40;
    int base = tid * CH;
    int sum = 0;
#pragma unroll 4
    for (int i = 0; i < CH; i++) { int idx = base + i; if (idx < NN) sum += d_counts[idx]; }
    int lane = tid & 31, wid = tid >> 5;
    int v = sum;
#pragma unroll
    for (int o = 1; o < 32; o <<= 1) { int t = __shfl_up_sync(0xffffffffu, v, o); if (lane >= o) v += t; }
    __shared__ int wsum[32];
    if (lane == 31) wsum[wid] = v;
    __syncthreads();
    if (wid == 0) {
        int w = wsum[lane];
#pragma unroll
        for (int o = 1; o < 32; o <<= 1) { int t = __shfl_up_sync(0xffffffffu, w, o); if (lane >= o) w += t; }
        wsum[lane] = w;
    }
    __syncthreads();
    int excl = v - sum + (wid ? wsum[wid - 1] : 0);
    int run = excl;
#pragma unroll 4
    for (int i = 0; i < CH; i++) {
        int idx = base + i;
        if (idx < NN) { d_offsets[idx] = run; run += d_counts[idx]; }
    }
    if (tid == 1023) d_offsets[NN] = run;
}

__global__ void fill_kernel(const int* __restrict__ ei) {
    int i = blockIdx.x * blockDim.x + threadIdx.x;
    int stride = gridDim.x * blockDim.x;
    for (int e = i; e < NE; e += stride) {
        int c = ei[NE + e];
        int p = atomicAdd(&d_cursor[c], 1);
        d_csr[d_offsets[c] + p] = e;
    }
}

__global__ __launch_bounds__(512) void prep_kernel(GateW gw) {
    int b = blockIdx.x;
    int c = threadIdx.x;
    int g = c >> 7, j = c & 127;
    if (b < 64) {
        int k = b;
        const float* wx = gw.wx[g];
        const float* wh = gw.wh[g];
        float acc = 0.f;
#pragma unroll 8
        for (int m = 0; m < FOUT; m++) acc += wx[k * FOUT + m] * wh[m * FOUT + j];
        d_W1[k * GC + c] = acc;
    } else if (b < 192) {
        int k = b - 64;
        d_W2[k * GC + c] = gw.wh[g][(FOUT + k) * FOUT + j];
    } else {
        float acc = gw.bh[g][j];
        for (int m = 0; m < FOUT; m++) acc += gw.bx[g][m] * gw.wh[g][m * FOUT + j];
        d_bias[c] = acc;
        if (c == 0) {
            float a[NP], mx = -1e30f, s = 0.f;
            for (int t = 0; t < NP; t++) { a[t] = gw.att[t]; mx = fmaxf(mx, a[t]); }
            for (int t = 0; t < NP; t++) { a[t] = expf(a[t] - mx); s += a[t]; }
            for (int t = 0; t < NP; t++) d_probs[t] = a[t] / s;
        }
    }
}

__global__ __launch_bounds__(768) void spmm_kernel(const float* __restrict__ X,
                                                   const int* __restrict__ ei,
                                                   const float* __restrict__ ew) {
    __shared__ int   srow[64];
    __shared__ float snrm[64];
    __shared__ float sval[FTOT];
    int n = blockIdx.x;
    int tid = threadIdx.x;
    float dn = d_dinv[n];
    float acc = dn * dn * X[n * FTOT + tid];
    int beg = d_offsets[n], end = d_offsets[n + 1];
    for (int eb = beg; eb < end; eb += 64) {
        int cnt = min(64, end - eb);
        if (tid < cnt) {
            int e = d_csr[eb + tid];
            int r = ei[e];
            srow[tid] = r;
            snrm[tid] = d_dinv[r] * ew[e] * dn;
        }
        __syncthreads();
#pragma unroll 4
        for (int i = 0; i < cnt; i++)
            acc += snrm[i] * X[srow[i] * FTOT + tid];
        __syncthreads();
    }
    sval[tid] = acc;
    __syncthreads();
    int t = tid >> 6, f = tid & 63;
    d_S[(size_t)t * NN * FIN + (size_t)n * FIN + f] = sval[f * NP + t];
}

// ---------------- FFMA2 step kernel ----------------
// Grid: 625 CTAs. CTA: 64 nodes x all 512 cols, 512 threads.
// Thread tile: 8 nodes (ty*8..) x 8 cols (tx*4.. and 256+tx*4..)  -> 32 f32x2 accs.
// K = 192 in 12 chunks of 16, cp.async double-buffered.
// SMEM: B chunks 2 x 32KB at [0,64K); A chunks 2 x 4KB at [64K, 72K).
// Epilogue: Z staged in 2 node-halves (32x512 f32 = 64KB) overlaying B buffers.
#define SM_B     0
#define SM_A     65536
#define SMEM_TOT (65536 + 8192)

__device__ __forceinline__ void load_chunk(uint32_t sb, int buf, int c, int t,
                                           int node0, int tid) {
    if (tid < 256) {
        int row = tid >> 2, q = tid & 3;
        int node = node0 + row;
        const float* src = (c < 4)
            ? &d_S[(size_t)t * NN * FIN + (size_t)node * FIN + c * 16 + q * 4]
            : &d_H[(size_t)node * FOUT + (c - 4) * 16 + q * 4];
        cp16(sb + SM_A + buf * 4096 + row * 64 + q * 16, src);
    }
#pragma unroll
    for (int i = 0; i < 4; i++) {
        int op = tid + 512 * i;            // 0..2047
        int row = op >> 7, q = op & 127;   // row 0..15, q 0..127 (16B units)
        const float* src = (c < 4) ? &d_W1[(c * 16 + row) * GC + q * 4]
                                   : &d_W2[((c - 4) * 16 + row) * GC + q * 4];
        cp16(sb + SM_B + buf * 32768 + row * 2048 + q * 16, src);
    }
}

__global__ __launch_bounds__(512) void step_ffma_kernel(int t, float* __restrict__ Hacc) {
    extern __shared__ char smem[];
    uint32_t sb = smem_u32(smem);
    int tid = threadIdx.x;
    int tx = tid & 63;        // col group
    int ty = tid >> 6;        // node group (0..7)
    int node0 = blockIdx.x * BN;

    unsigned long long acc[8][4];
#pragma unroll
    for (int i = 0; i < 8; i++)
#pragma unroll
        for (int j = 0; j < 4; j++) acc[i][j] = 0ull;

    load_chunk(sb, 0, 0, t, node0, tid);
    CP_COMMIT();

    for (int c = 0; c < 12; c++) {
        if (c < 11) {
            load_chunk(sb, (c + 1) & 1, c + 1, t, node0, tid);
            CP_COMMIT();
            CP_WAIT(1);
        } else {
            CP_WAIT(0);
        }
        __syncthreads();

        const float4* Bf4 = (const float4*)(smem + SM_B + (c & 1) * 32768);
        const float*  Af  = (const float*)(smem + SM_A + (c & 1) * 4096);

#pragma unroll
        for (int kk = 0; kk < 16; kk++) {
            float4 b0 = Bf4[kk * 128 + tx];         // cols tx*4..+3
            float4 b1 = Bf4[kk * 128 + 64 + tx];    // cols 256+tx*4..+3
            unsigned long long bb0 = pack2(b0.x, b0.y);
            unsigned long long bb1 = pack2(b0.z, b0.w);
            unsigned long long bb2 = pack2(b1.x, b1.y);
            unsigned long long bb3 = pack2(b1.z, b1.w);
#pragma unroll
            for (int i = 0; i < 8; i++) {
                unsigned long long aa = pk2(Af[(ty * 8 + i) * 16 + kk]);
                acc[i][0] = f2fma(aa, bb0, acc[i][0]);
                acc[i][1] = f2fma(aa, bb1, acc[i][1]);
                acc[i][2] = f2fma(aa, bb2, acc[i][2]);
                acc[i][3] = f2fma(aa, bb3, acc[i][3]);
            }
        }
        __syncthreads();   // protect buffer (c+1)&1... actually buffer c&1 reuse at iter c+1
    }

    // ---- epilogue: two halves of 32 nodes, Z staged over B buffers ----
    float* Zf = (float*)smem;
    float p = d_probs[t];
    int nd = tid >> 4, j8 = (tid & 15) * 8;

#pragma unroll
    for (int h = 0; h < 2; h++) {
        if ((ty >> 2) == h) {
            int l0 = (ty & 3) * 8;
#pragma unroll
            for (int i = 0; i < 8; i++) {
                float2 z0 = up2(acc[i][0]), z1 = up2(acc[i][1]);
                float2 z2 = up2(acc[i][2]), z3 = up2(acc[i][3]);
                *(float4*)&Zf[(l0 + i) * 512 + tx * 4] = make_float4(z0.x, z0.y, z1.x, z1.y);
                *(float4*)&Zf[(l0 + i) * 512 + 256 + tx * 4] = make_float4(z2.x, z2.y, z3.x, z3.y);
            }
        }
        __syncthreads();

        {
            int node = node0 + h * 32 + nd;
            float hv[8], cv[8], av[8];
            int gbase = node * FOUT + j8;
#pragma unroll
            for (int u = 0; u < 8; u++) {
                int j = j8 + u;
                float zi = Zf[nd * 512 + j]       + d_bias[j];
                float zf = Zf[nd * 512 + 128 + j] + d_bias[128 + j];
                float zc = Zf[nd * 512 + 256 + j] + d_bias[256 + j];
                float zo = Zf[nd * 512 + 384 + j] + d_bias[384 + j];
                float I  = 1.f / (1.f + __expf(-zi));
                float F  = 1.f / (1.f + __expf(-zf));
                float Ct = 1.f - 2.f / (__expf(2.f * zc) + 1.f);
                float O  = 1.f / (1.f + __expf(-zo));
                float cn = F * d_C[gbase + u] + I * Ct;
                float hh = O * (1.f - 2.f / (__expf(2.f * cn) + 1.f));
                hv[u] = hh; cv[u] = cn;
                av[u] = (t == 0 ? 0.f : Hacc[gbase + u]) + p * hh;
            }
            *(float4*)&d_H[gbase]     = make_float4(hv[0], hv[1], hv[2], hv[3]);
            *(float4*)&d_H[gbase + 4] = make_float4(hv[4], hv[5], hv[6], hv[7]);
            *(float4*)&d_C[gbase]     = make_float4(cv[0], cv[1], cv[2], cv[3]);
            *(float4*)&d_C[gbase + 4] = make_float4(cv[4], cv[5], cv[6], cv[7]);
            *(float4*)&Hacc[gbase]     = make_float4(av[0], av[1], av[2], av[3]);
            *(float4*)&Hacc[gbase + 4] = make_float4(av[4], av[5], av[6], av[7]);
        }
        __syncthreads();
    }
}

// ---------------- launch ----------------
extern "C" void kernel_launch(void* const* d_in, const int* in_sizes, int n_in,
                              void* d_out, int out_size) {
    const float* X   = (const float*)d_in[0];
    const int*   ei  = (const int*)d_in[1];
    const float* ew  = (const float*)d_in[2];
    const float* att = (const float*)d_in[3];
    GateW gw;
    for (int g = 0; g < 4; g++) {
        gw.wx[g] = (const float*)d_in[4 + 4 * g];
        gw.bx[g] = (const float*)d_in[5 + 4 * g];
        gw.wh[g] = (const float*)d_in[6 + 4 * g];
        gw.bh[g] = (const float*)d_in[7 + 4 * g];
    }
    gw.att = att;
    float* out = (float*)d_out;

    cudaFuncSetAttribute(step_ffma_kernel, cudaFuncAttributeMaxDynamicSharedMemorySize, SMEM_TOT);

    zero_kernel<<<512, 256>>>();
    deg_kernel<<<640, 256>>>(ei, ew);
    scan_kernel<<<1, 1024>>>();
    fill_kernel<<<640, 256>>>(ei);
    prep_kernel<<<193, 512>>>(gw);
    spmm_kernel<<<NN, 768>>>(X, ei, ew);
    for (int t = 0; t < NP; t++)
        step_ffma_kernel<<<NN / BN, 512, SMEM_TOT>>>(t, out);
}